// round 1
// baseline (speedup 1.0000x reference)
#include <cuda_runtime.h>
#include <math.h>

#define D      2048
#define NEXP   64
#define BM     64
#define BK     64
#define NTHR   256

// Pre-normalized prototypes + their element sums (scratch: __device__ globals, no allocs)
__device__ float g_pn[NEXP * D];
__device__ float g_psum[NEXP];

// ---------------------------------------------------------------------------
// Kernel 1: unit-normalize prototypes, compute sum of each normalized row.
// 64 blocks x 256 threads. Tiny (~3 us).
// ---------------------------------------------------------------------------
__global__ __launch_bounds__(256) void proto_norm_kernel(const float* __restrict__ p) {
    const int e = blockIdx.x;
    const int t = threadIdx.x;
    const float* row = p + (size_t)e * D;

    __shared__ float red[256];

    float ss = 0.f;
    for (int i = t; i < D; i += 256) {
        float v = row[i];
        ss = fmaf(v, v, ss);
    }
    red[t] = ss;
    __syncthreads();
    for (int s = 128; s > 0; s >>= 1) {
        if (t < s) red[t] += red[t + s];
        __syncthreads();
    }
    const float nrm = sqrtf(red[0]);
    const float inv = 1.f / fmaxf(nrm, 1e-8f);
    __syncthreads();

    float sum = 0.f;
    for (int i = t; i < D; i += 256) {
        float v = row[i] * inv;
        g_pn[(size_t)e * D + i] = v;
        sum += v;
    }
    red[t] = sum;
    __syncthreads();
    for (int s = 128; s > 0; s >>= 1) {
        if (t < s) red[t] += red[t + s];
        __syncthreads();
    }
    if (t == 0) g_psum[e] = red[0];
}

// ---------------------------------------------------------------------------
// Kernel 2: fused GEMM (x @ pn^T) + row stats + layernorm-correction +
//           top-2 + pair softmax.
//   logit_e = (dot(x, pn_e) - mu * psum_e) / sigma / TEMP
//   w1 = 1/(1 + exp(l2 - l1)), w2 = 1 - w1   (softmax denominator cancels)
// BM=64 tokens per CTA, all 64 experts, BK=64 K-chunks, 4x4 micro-tiles.
// ---------------------------------------------------------------------------
__global__ __launch_bounds__(NTHR) void router_kernel(
    const float* __restrict__ x,
    float* __restrict__ out_w,     // [ntok, 2]
    float* __restrict__ out_i,     // [ntok, 2] (indices as float), may be null
    int write_idx)
{
    // As/Bs live during the GEMM; lg (logits) only after. Union them.
    __shared__ __align__(16) union {
        struct {
            float As[BK][BM];     // x tile, transposed  (16 KB)
            float Bs[BK][NEXP];   // pn tile, transposed (16 KB)
        } t;
        float lg[BM][NEXP + 1];   // padded logits (16.25 KB)
    } sm;
    __shared__ float s1s[NTHR];
    __shared__ float s2s[NTHR];

    const int tid  = threadIdx.x;
    const int row  = tid >> 2;          // 0..63  : fixed token-row / expert-row for loads
    const int cseg = (tid & 3) * 16;    // 0/16/32/48 : 16-float column segment within BK
    const int ty   = tid >> 4;          // 0..15 : micro-tile row group
    const int tx   = tid & 15;          // 0..15 : micro-tile col group
    const int tokBase = blockIdx.x * BM;

    const float* xg = x    + (size_t)(tokBase + row) * D + cseg;
    const float* pg = g_pn + (size_t)row * D + cseg;

    float acc[4][4];
#pragma unroll
    for (int i = 0; i < 4; i++)
#pragma unroll
        for (int j = 0; j < 4; j++) acc[i][j] = 0.f;

    float s1 = 0.f, s2 = 0.f;

    for (int k0 = 0; k0 < D; k0 += BK) {
        // ---- load tiles (transposed into smem), fuse row stats on x ----
#pragma unroll
        for (int j = 0; j < 4; j++) {
            float4 v = *(const float4*)(xg + k0 + j * 4);
            int kk = cseg + j * 4;
            sm.t.As[kk + 0][row] = v.x;
            sm.t.As[kk + 1][row] = v.y;
            sm.t.As[kk + 2][row] = v.z;
            sm.t.As[kk + 3][row] = v.w;
            s1 += v.x + v.y + v.z + v.w;
            s2 = fmaf(v.x, v.x, s2);
            s2 = fmaf(v.y, v.y, s2);
            s2 = fmaf(v.z, v.z, s2);
            s2 = fmaf(v.w, v.w, s2);

            float4 w = *(const float4*)(pg + k0 + j * 4);
            sm.t.Bs[kk + 0][row] = w.x;
            sm.t.Bs[kk + 1][row] = w.y;
            sm.t.Bs[kk + 2][row] = w.z;
            sm.t.Bs[kk + 3][row] = w.w;
        }
        __syncthreads();

        // ---- 4x4 micro-tile FMA over BK ----
#pragma unroll
        for (int k = 0; k < BK; k++) {
            float4 a = *(const float4*)&sm.t.As[k][ty * 4];
            float4 b = *(const float4*)&sm.t.Bs[k][tx * 4];
            acc[0][0] = fmaf(a.x, b.x, acc[0][0]);
            acc[0][1] = fmaf(a.x, b.y, acc[0][1]);
            acc[0][2] = fmaf(a.x, b.z, acc[0][2]);
            acc[0][3] = fmaf(a.x, b.w, acc[0][3]);
            acc[1][0] = fmaf(a.y, b.x, acc[1][0]);
            acc[1][1] = fmaf(a.y, b.y, acc[1][1]);
            acc[1][2] = fmaf(a.y, b.z, acc[1][2]);
            acc[1][3] = fmaf(a.y, b.w, acc[1][3]);
            acc[2][0] = fmaf(a.z, b.x, acc[2][0]);
            acc[2][1] = fmaf(a.z, b.y, acc[2][1]);
            acc[2][2] = fmaf(a.z, b.z, acc[2][2]);
            acc[2][3] = fmaf(a.z, b.w, acc[2][3]);
            acc[3][0] = fmaf(a.w, b.x, acc[3][0]);
            acc[3][1] = fmaf(a.w, b.y, acc[3][1]);
            acc[3][2] = fmaf(a.w, b.z, acc[3][2]);
            acc[3][3] = fmaf(a.w, b.w, acc[3][3]);
        }
        __syncthreads();
    }

    // ---- stash stats + logits in smem ----
    s1s[tid] = s1;
    s2s[tid] = s2;
#pragma unroll
    for (int i = 0; i < 4; i++) {
        int r = ty * 4 + i;
#pragma unroll
        for (int j = 0; j < 4; j++)
            sm.lg[r][tx * 4 + j] = acc[i][j];
    }
    __syncthreads();

    // ---- epilogue: 1 thread per token ----
    if (tid < BM) {
        const int r = tid;
        float S1 = s1s[r * 4] + s1s[r * 4 + 1] + s1s[r * 4 + 2] + s1s[r * 4 + 3];
        float S2 = s2s[r * 4] + s2s[r * 4 + 1] + s2s[r * 4 + 2] + s2s[r * 4 + 3];
        const float mu   = S1 * (1.f / D);
        const float var  = S2 * (1.f / D) - mu * mu;
        const float rinv = rsqrtf(var + 1e-5f) * 0.125f;   // fold 1/TEMP

        float best1 = -1e30f, best2 = -1e30f;
        int   i1 = 0, i2 = 0;
#pragma unroll 8
        for (int e = 0; e < NEXP; e++) {
            float l = (sm.lg[r][e] - mu * g_psum[e]) * rinv;
            if (l > best1)      { best2 = best1; i2 = i1; best1 = l; i1 = e; }
            else if (l > best2) { best2 = l; i2 = e; }
        }
        // pair softmax (global Z cancels after renormalization)
        float ed = expf(best2 - best1);
        float w1 = 1.f / (1.f + ed);
        float w2 = ed / (1.f + ed);

        const int tok = tokBase + r;
        out_w[tok * 2 + 0] = w1;
        out_w[tok * 2 + 1] = w2;
        if (write_idx) {
            out_i[tok * 2 + 0] = (float)i1;
            out_i[tok * 2 + 1] = (float)i2;
        }
    }
}

// ---------------------------------------------------------------------------
extern "C" void kernel_launch(void* const* d_in, const int* in_sizes, int n_in,
                              void* d_out, int out_size) {
    const float* x = (const float*)d_in[0];   // [4,4096,2048] f32
    const float* p = (const float*)d_in[1];   // [64,2048] f32
    float* out = (float*)d_out;

    const int ntok = in_sizes[0] / D;         // 16384
    // out layout: top_w flattened first; if there's room, top_i (as float) after.
    const int write_idx = (out_size >= 4 * ntok) ? 1 : 0;
    float* out_i = out + 2 * ntok;

    proto_norm_kernel<<<NEXP, 256>>>(p);
    router_kernel<<<ntok / BM, NTHR>>>(x, out, out_i, write_idx);
}

// round 2
// speedup vs baseline: 1.0560x; 1.0560x over previous
#include <cuda_runtime.h>
#include <math.h>

#define D      2048
#define NEXP   64
#define BM     64
#define BK     32
#define NTHR   256
#define NCH    (D / BK)   // 64 chunks

typedef unsigned long long u64;

// packed fp32x2 FMA: d = a*b + d (elementwise on (lo,hi) pairs)
__device__ __forceinline__ void fma2(u64& d, u64 a, u64 b) {
    asm("fma.rn.f32x2 %0, %1, %2, %0;" : "+l"(d) : "l"(a), "l"(b));
}
__device__ __forceinline__ void unpack2(u64 v, float& lo, float& hi) {
    asm("mov.b64 {%0, %1}, %2;" : "=f"(lo), "=f"(hi) : "l"(v));
}

// Pre-normalized prototypes + their element sums
__device__ float g_pn[NEXP * D];
__device__ float g_psum[NEXP];

// ---------------------------------------------------------------------------
// Kernel 1: unit-normalize prototypes, compute per-row sums. Tiny.
// ---------------------------------------------------------------------------
__global__ __launch_bounds__(256) void proto_norm_kernel(const float* __restrict__ p) {
    const int e = blockIdx.x;
    const int t = threadIdx.x;
    const float* row = p + (size_t)e * D;

    __shared__ float red[256];

    float ss = 0.f;
    for (int i = t; i < D; i += 256) {
        float v = row[i];
        ss = fmaf(v, v, ss);
    }
    red[t] = ss;
    __syncthreads();
    for (int s = 128; s > 0; s >>= 1) {
        if (t < s) red[t] += red[t + s];
        __syncthreads();
    }
    const float inv = 1.f / fmaxf(sqrtf(red[0]), 1e-8f);
    __syncthreads();

    float sum = 0.f;
    for (int i = t; i < D; i += 256) {
        float v = row[i] * inv;
        g_pn[(size_t)e * D + i] = v;
        sum += v;
    }
    red[t] = sum;
    __syncthreads();
    for (int s = 128; s > 0; s >>= 1) {
        if (t < s) red[t] += red[t + s];
        __syncthreads();
    }
    if (t == 0) g_psum[e] = red[0];
}

// ---------------------------------------------------------------------------
// Kernel 2: fused GEMM + LN-stats + top-2 + pair-softmax, FFMA2 inner loop.
//   logit_e = (dot(x, pn_e) - mu * psum_e) / sigma / TEMP
//   top-2 weights: w1 = 1/(1+e^{l2-l1}) (softmax denominator cancels)
// ---------------------------------------------------------------------------
__global__ __launch_bounds__(NTHR) void router_kernel(
    const float* __restrict__ x,
    float* __restrict__ out_w,
    float* __restrict__ out_i,
    int write_idx)
{
    __shared__ __align__(16) union {
        struct {
            float2 As[BK][BM];     // token-duplicated (v,v), xor-swizzled  16 KB
            float  Bs[BK][NEXP];   // xor-swizzled                           8 KB
        } t;
        float lg[BM][NEXP + 1];    // logits after GEMM                   16.25 KB
    } sm;
    __shared__ float s1s[NTHR];
    __shared__ float s2s[NTHR];

    const int tid  = threadIdx.x;
    const int row  = tid >> 2;          // 0..63 token-row / expert-row for loads
    const int cseg = (tid & 3) * 8;     // 8-float K-segment within BK
    const int soff = (tid & 3) * 8;     // store swizzle offset = ((kk>>3)&3)*8
    const int ty   = tid >> 4;          // 0..15
    const int tx   = tid & 15;          // 0..15
    const int tokBase = blockIdx.x * BM;

    const float* xg = x    + (size_t)(tokBase + row) * D + cseg;
    const float* pg = g_pn + (size_t)row * D + cseg;

    u64 acc[4][2];
#pragma unroll
    for (int i = 0; i < 4; i++) { acc[i][0] = 0ull; acc[i][1] = 0ull; }

    float s1 = 0.f, s2 = 0.f;

    // prefetch chunk 0 into registers
    float4 xr0 = *(const float4*)(xg + 0);
    float4 xr1 = *(const float4*)(xg + 4);
    float4 pr0 = *(const float4*)(pg + 0);
    float4 pr1 = *(const float4*)(pg + 4);

    const int scol = row ^ soff;

    for (int c = 0; c < NCH; c++) {
        // ---- store prefetched regs to smem (swizzled), fuse x row stats ----
        {
            float xv[8] = {xr0.x, xr0.y, xr0.z, xr0.w, xr1.x, xr1.y, xr1.z, xr1.w};
            float pv[8] = {pr0.x, pr0.y, pr0.z, pr0.w, pr1.x, pr1.y, pr1.z, pr1.w};
#pragma unroll
            for (int j = 0; j < 8; j++) {
                const int kk = cseg + j;
                float v = xv[j];
                sm.t.As[kk][scol] = make_float2(v, v);
                sm.t.Bs[kk][scol] = pv[j];
                s1 += v;
                s2 = fmaf(v, v, s2);
            }
        }
        __syncthreads();

        // ---- prefetch next chunk (LDGs fly during the FMA loop) ----
        if (c + 1 < NCH) {
            const float* xp = xg + (c + 1) * BK;
            const float* pp = pg + (c + 1) * BK;
            xr0 = *(const float4*)(xp + 0);
            xr1 = *(const float4*)(xp + 4);
            pr0 = *(const float4*)(pp + 0);
            pr1 = *(const float4*)(pp + 4);
        }

        // ---- FFMA2 micro-kernel: 4 tokens x 4 experts (2 packed pairs) ----
#pragma unroll
        for (int k = 0; k < BK; k++) {
            const int off = ((k >> 3) & 3) * 8;
            const float2* ap = &sm.t.As[k][(ty * 4) ^ off];
            ulonglong2 a01 = *(const ulonglong2*)ap;
            ulonglong2 a23 = *(const ulonglong2*)(ap + 2);
            ulonglong2 bb  = *(const ulonglong2*)&sm.t.Bs[k][(tx * 4) ^ off];
            fma2(acc[0][0], a01.x, bb.x); fma2(acc[0][1], a01.x, bb.y);
            fma2(acc[1][0], a01.y, bb.x); fma2(acc[1][1], a01.y, bb.y);
            fma2(acc[2][0], a23.x, bb.x); fma2(acc[2][1], a23.x, bb.y);
            fma2(acc[3][0], a23.y, bb.x); fma2(acc[3][1], a23.y, bb.y);
        }
        __syncthreads();
    }

    // ---- stash stats + logits in smem ----
    s1s[tid] = s1;
    s2s[tid] = s2;
#pragma unroll
    for (int i = 0; i < 4; i++) {
        const int r = ty * 4 + i;
        float lo, hi;
        unpack2(acc[i][0], lo, hi);
        sm.lg[r][tx * 4 + 0] = lo;
        sm.lg[r][tx * 4 + 1] = hi;
        unpack2(acc[i][1], lo, hi);
        sm.lg[r][tx * 4 + 2] = lo;
        sm.lg[r][tx * 4 + 3] = hi;
    }
    __syncthreads();

    // ---- epilogue: 1 thread per token ----
    if (tid < BM) {
        const int r = tid;
        float S1 = s1s[r * 4] + s1s[r * 4 + 1] + s1s[r * 4 + 2] + s1s[r * 4 + 3];
        float S2 = s2s[r * 4] + s2s[r * 4 + 1] + s2s[r * 4 + 2] + s2s[r * 4 + 3];
        const float mu   = S1 * (1.f / D);
        const float var  = S2 * (1.f / D) - mu * mu;
        const float rinv = rsqrtf(var + 1e-5f) * 0.125f;   // fold 1/TEMP

        float best1 = -1e30f, best2 = -1e30f;
        int   i1 = 0, i2 = 0;
#pragma unroll 8
        for (int e = 0; e < NEXP; e++) {
            float l = (sm.lg[r][e] - mu * g_psum[e]) * rinv;
            if (l > best1)      { best2 = best1; i2 = i1; best1 = l; i1 = e; }
            else if (l > best2) { best2 = l; i2 = e; }
        }
        float ed = expf(best2 - best1);
        float w1 = 1.f / (1.f + ed);
        float w2 = ed / (1.f + ed);

        const int tok = tokBase + r;
        out_w[tok * 2 + 0] = w1;
        out_w[tok * 2 + 1] = w2;
        if (write_idx) {
            out_i[tok * 2 + 0] = (float)i1;
            out_i[tok * 2 + 1] = (float)i2;
        }
    }
}

// ---------------------------------------------------------------------------
extern "C" void kernel_launch(void* const* d_in, const int* in_sizes, int n_in,
                              void* d_out, int out_size) {
    const float* x = (const float*)d_in[0];   // [4,4096,2048] f32
    const float* p = (const float*)d_in[1];   // [64,2048] f32
    float* out = (float*)d_out;

    const int ntok = in_sizes[0] / D;         // 16384
    const int write_idx = (out_size >= 4 * ntok) ? 1 : 0;
    float* out_i = out + 2 * ntok;

    proto_norm_kernel<<<NEXP, 256>>>(p);
    router_kernel<<<ntok / BM, NTHR>>>(x, out, out_i, write_idx);
}

// round 4
// speedup vs baseline: 1.4846x; 1.4059x over previous
#include <cuda_runtime.h>
#include <math.h>
#include <stdint.h>

#define D        2048
#define NEXP     64
#define BM       128
#define KC       32
#define NCHUNK   (D / KC)     // 64
#define NTHR     128
#define LG_STRIDE 66

// smem layout (bytes)
#define A_TILE   16384        // per (buf,split): 128 rows x 32 floats x 4B
#define B_TILE   8192         // per (buf,split): 64 rows x 32 floats x 4B
#define OFF_A    0
#define OFF_B    (4 * A_TILE)             // 65536
#define OFF_PSUM (OFF_B + 4 * B_TILE)     // 98304
#define SMEM_TOTAL (OFF_PSUM + 256)

// Prototype tf32 splits, swizzled per chunk: [chunk][split][n][c]  (1 MB, L2-resident)
__device__ __align__(16) float g_pb[NCHUNK * 2 * NEXP * KC];
__device__ float g_psum[NEXP];

// ---------------- PTX helpers (baseline sm_80+, no 'a' features) ----------------
__device__ __forceinline__ uint32_t cvta_s(const void* p) {
    uint32_t a;
    asm("{ .reg .u64 t; cvta.to.shared.u64 t, %1; cvt.u32.u64 %0, t; }" : "=r"(a) : "l"(p));
    return a;
}
__device__ __forceinline__ uint32_t tf32_of(float f) {
    uint32_t r;
    asm("cvt.rna.tf32.f32 %0, %1;" : "=r"(r) : "f"(f));
    return r;
}
__device__ __forceinline__ void cp16(uint32_t dst, const void* src) {
    asm volatile("cp.async.ca.shared.global [%0], [%1], 16;" :: "r"(dst), "l"(src));
}
#define CP_COMMIT() asm volatile("cp.async.commit_group;")
#define CP_WAIT0()  asm volatile("cp.async.wait_group 0;")

#define MMA(Cf, A_, B_) asm volatile( \
    "mma.sync.aligned.m16n8k8.row.col.f32.tf32.tf32.f32 " \
    "{%0,%1,%2,%3}, {%4,%5,%6,%7}, {%8,%9}, {%0,%1,%2,%3};" \
    : "+f"((Cf)[0]), "+f"((Cf)[1]), "+f"((Cf)[2]), "+f"((Cf)[3]) \
    : "r"((A_)[0]), "r"((A_)[1]), "r"((A_)[2]), "r"((A_)[3]), \
      "r"((B_)[0]), "r"((B_)[1]))

// ---------------------------------------------------------------------------
// Kernel 1: unit-normalize prototypes, tf32 2-way split, swizzled layout.
// ---------------------------------------------------------------------------
__global__ __launch_bounds__(256) void proto_prep_kernel(const float* __restrict__ p) {
    const int e = blockIdx.x;
    const int t = threadIdx.x;
    const float* row = p + (size_t)e * D;

    __shared__ float red[256];

    float ss = 0.f;
    for (int i = t; i < D; i += 256) { float v = row[i]; ss = fmaf(v, v, ss); }
    red[t] = ss;
    __syncthreads();
    for (int s = 128; s > 0; s >>= 1) { if (t < s) red[t] += red[t + s]; __syncthreads(); }
    const float inv = 1.f / fmaxf(sqrtf(red[0]), 1e-8f);
    __syncthreads();

    const int xo = 4 * (e & 7);
    float sum = 0.f;
    for (int i = t; i < D; i += 256) {
        float v = row[i] * inv;
        sum += v;
        uint32_t u1 = tf32_of(v);
        uint32_t u2 = tf32_of(v - __uint_as_float(u1));
        const int ch = i >> 5;
        const int cc = (i & 31) ^ xo;
        g_pb[(ch * 2 + 0) * (NEXP * KC) + e * KC + cc] = __uint_as_float(u1);
        g_pb[(ch * 2 + 1) * (NEXP * KC) + e * KC + cc] = __uint_as_float(u2);
    }
    red[t] = sum;
    __syncthreads();
    for (int s = 128; s > 0; s >>= 1) { if (t < s) red[t] += red[t + s]; __syncthreads(); }
    if (t == 0) g_psum[e] = red[0];
}

// ---------------------------------------------------------------------------
// Kernel 2: tf32 mma.sync router. 128 tokens/CTA, 4 warps (m32n64 each),
// double-buffered smem, 3 split-products, fused LN stats + top-2 epilogue.
// ---------------------------------------------------------------------------
__global__ __launch_bounds__(NTHR, 1) void router_kernel(
    const float* __restrict__ x,
    float* __restrict__ out_w,
    float* __restrict__ out_i,
    int write_idx)
{
    extern __shared__ __align__(16) unsigned char smem[];
    float* sA = (float*)(smem + OFF_A);
    float* sB = (float*)(smem + OFF_B);
    float* sP = (float*)(smem + OFF_PSUM);

    const int tid  = threadIdx.x;
    const int lane = tid & 31;
    const int warp = tid >> 5;
    const int tokBase = blockIdx.x * BM;

    if (tid < NEXP) sP[tid] = g_psum[tid];

    const int m = tid;                         // this thread owns token row m
    const float* xrow = x + (size_t)(tokBase + m) * D;
    const int xor4m = 4 * (m & 7);

    const uint32_t sB_u32 = cvta_s(sB);

    float s1 = 0.f, s2 = 0.f;
    float C[16][4];
#pragma unroll
    for (int f = 0; f < 16; f++) { C[f][0] = C[f][1] = C[f][2] = C[f][3] = 0.f; }

    float4 xr[8];

    // ---- prologue: chunk 0 ----
#pragma unroll
    for (int g = 0; g < 8; g++) xr[g] = ((const float4*)xrow)[g];
    {   // B cp.async chunk 0 -> buf 0
        const float* src = g_pb;
#pragma unroll
        for (int i = 0; i < 8; i++) {
            const int j = tid + i * NTHR;      // float4 index within 16KB
            cp16(sB_u32 + j * 16, src + j * 4);
        }
        CP_COMMIT();
    }
    {   // convert + store A chunk 0 -> buf 0
        float* a1p = sA + 0 * (A_TILE / 4) + m * KC;
        float* a2p = sA + 1 * (A_TILE / 4) + m * KC;
#pragma unroll
        for (int g = 0; g < 8; g++) {
            float4 v = xr[g];
            s1 += v.x + v.y + v.z + v.w;
            s2 = fmaf(v.x, v.x, s2); s2 = fmaf(v.y, v.y, s2);
            s2 = fmaf(v.z, v.z, s2); s2 = fmaf(v.w, v.w, s2);
            uint4 u1, u2;
            u1.x = tf32_of(v.x); u2.x = tf32_of(v.x - __uint_as_float(u1.x));
            u1.y = tf32_of(v.y); u2.y = tf32_of(v.y - __uint_as_float(u1.y));
            u1.z = tf32_of(v.z); u2.z = tf32_of(v.z - __uint_as_float(u1.z));
            u1.w = tf32_of(v.w); u2.w = tf32_of(v.w - __uint_as_float(u1.w));
            const int cc = (g * 4) ^ xor4m;
            *(uint4*)(a1p + cc) = u1;
            *(uint4*)(a2p + cc) = u2;
        }
    }
    CP_WAIT0();
    __syncthreads();

    const int np = lane >> 2;       // 0..7
    const int kq = lane & 3;        // 0..3
    const int xorb = 4 * np;

    // ---- main loop ----
    for (int c = 0; c < NCHUNK; c++) {
        const int buf = c & 1, nb = buf ^ 1;

        if (c + 1 < NCHUNK) {
            // B cp.async for next chunk into other buffer (safe: last read 2 syncs ago)
            const float* src = g_pb + (size_t)(c + 1) * 2 * (NEXP * KC);
            const uint32_t dstb = sB_u32 + nb * 2 * B_TILE;
#pragma unroll
            for (int i = 0; i < 8; i++) {
                const int j = tid + i * NTHR;
                cp16(dstb + j * 16, src + j * 4);
            }
            CP_COMMIT();
            // x LDG for next chunk (latency hidden under mma pass)
            const float4* xs = (const float4*)(xrow + (c + 1) * KC);
#pragma unroll
            for (int g = 0; g < 8; g++) xr[g] = xs[g];
        }

        // ---- mma pass on buf ----
        {
            const float* Bb0 = sB + (buf * 2 + 0) * (B_TILE / 4);
            const float* Bb1 = sB + (buf * 2 + 1) * (B_TILE / 4);
            const float* Ab0 = sA + (buf * 2 + 0) * (A_TILE / 4);
            const float* Ab1 = sA + (buf * 2 + 1) * (A_TILE / 4);
#pragma unroll
            for (int s = 0; s < 4; s++) {
                const int k0 = s * 8;
                const int c0 = (k0 + kq) ^ xorb;
                const int c1 = (k0 + 4 + kq) ^ xorb;
                uint32_t b[2][8][2];
#pragma unroll
                for (int nt = 0; nt < 8; nt++) {
                    const int ro = (nt * 8 + np) * KC;
                    b[0][nt][0] = __float_as_uint(Bb0[ro + c0]);
                    b[0][nt][1] = __float_as_uint(Bb0[ro + c1]);
                    b[1][nt][0] = __float_as_uint(Bb1[ro + c0]);
                    b[1][nt][1] = __float_as_uint(Bb1[ro + c1]);
                }
                const int ca0 = (k0 + kq) ^ (4 * np);   // row&7 == np for A frags too
                const int ca1 = (k0 + 4 + kq) ^ (4 * np);
                uint32_t a[2][4];
#pragma unroll
                for (int mt = 0; mt < 2; mt++) {
                    const float* Ap = Ab0 + (warp * 32 + mt * 16 + np) * KC;
                    a[mt][0] = __float_as_uint(Ap[ca0]);
                    a[mt][1] = __float_as_uint(Ap[8 * KC + ca0]);
                    a[mt][2] = __float_as_uint(Ap[ca1]);
                    a[mt][3] = __float_as_uint(Ap[8 * KC + ca1]);
                }
#pragma unroll
                for (int mt = 0; mt < 2; mt++)
#pragma unroll
                    for (int nt = 0; nt < 8; nt++) {
                        MMA(C[mt * 8 + nt], a[mt], b[0][nt]);   // x1*p1
                        MMA(C[mt * 8 + nt], a[mt], b[1][nt]);   // x1*p2
                    }
#pragma unroll
                for (int mt = 0; mt < 2; mt++) {
                    const float* Ap = Ab1 + (warp * 32 + mt * 16 + np) * KC;
                    a[mt][0] = __float_as_uint(Ap[ca0]);
                    a[mt][1] = __float_as_uint(Ap[8 * KC + ca0]);
                    a[mt][2] = __float_as_uint(Ap[ca1]);
                    a[mt][3] = __float_as_uint(Ap[8 * KC + ca1]);
                }
#pragma unroll
                for (int mt = 0; mt < 2; mt++)
#pragma unroll
                    for (int nt = 0; nt < 8; nt++)
                        MMA(C[mt * 8 + nt], a[mt], b[0][nt]);   // x2*p1
            }
        }

        if (c + 1 < NCHUNK) {
            // convert + store A for next chunk into other buffer
            float* a1p = sA + (nb * 2 + 0) * (A_TILE / 4) + m * KC;
            float* a2p = sA + (nb * 2 + 1) * (A_TILE / 4) + m * KC;
#pragma unroll
            for (int g = 0; g < 8; g++) {
                float4 v = xr[g];
                s1 += v.x + v.y + v.z + v.w;
                s2 = fmaf(v.x, v.x, s2); s2 = fmaf(v.y, v.y, s2);
                s2 = fmaf(v.z, v.z, s2); s2 = fmaf(v.w, v.w, s2);
                uint4 u1, u2;
                u1.x = tf32_of(v.x); u2.x = tf32_of(v.x - __uint_as_float(u1.x));
                u1.y = tf32_of(v.y); u2.y = tf32_of(v.y - __uint_as_float(u1.y));
                u1.z = tf32_of(v.z); u2.z = tf32_of(v.z - __uint_as_float(u1.z));
                u1.w = tf32_of(v.w); u2.w = tf32_of(v.w - __uint_as_float(u1.w));
                const int cc = (g * 4) ^ xor4m;
                *(uint4*)(a1p + cc) = u1;
                *(uint4*)(a2p + cc) = u2;
            }
            CP_WAIT0();
        }
        __syncthreads();
    }

    // ---- store logits to smem (reuse A region), stride 66 for conflict-free read ----
    float* lg = (float*)smem;
#pragma unroll
    for (int mt = 0; mt < 2; mt++)
#pragma unroll
        for (int nt = 0; nt < 8; nt++) {
            const int row = warp * 32 + mt * 16 + np;
            const int col = nt * 8 + 2 * kq;
            *(float2*)(lg + row * LG_STRIDE + col) =
                make_float2(C[mt * 8 + nt][0], C[mt * 8 + nt][1]);
            *(float2*)(lg + (row + 8) * LG_STRIDE + col) =
                make_float2(C[mt * 8 + nt][2], C[mt * 8 + nt][3]);
        }
    __syncthreads();

    // ---- epilogue: thread t = token t ----
    {
        const float mu   = s1 * (1.f / D);
        const float var  = s2 * (1.f / D) - mu * mu;
        const float rinv = rsqrtf(var + 1e-5f) * 0.125f;   // fold 1/TEMP

        const float* lrow = lg + m * LG_STRIDE;
        float best1 = -1e30f, best2 = -1e30f;
        int i1 = 0, i2 = 0;
#pragma unroll 8
        for (int e = 0; e < NEXP; e++) {
            float l = (lrow[e] - mu * sP[e]) * rinv;
            if (l > best1)      { best2 = best1; i2 = i1; best1 = l; i1 = e; }
            else if (l > best2) { best2 = l; i2 = e; }
        }
        float ed = expf(best2 - best1);
        float w1 = 1.f / (1.f + ed);
        float w2 = ed / (1.f + ed);

        const int tg = tokBase + m;
        out_w[tg * 2 + 0] = w1;
        out_w[tg * 2 + 1] = w2;
        if (write_idx) {
            out_i[tg * 2 + 0] = (float)i1;
            out_i[tg * 2 + 1] = (float)i2;
        }
    }
}

// ---------------------------------------------------------------------------
extern "C" void kernel_launch(void* const* d_in, const int* in_sizes, int n_in,
                              void* d_out, int out_size) {
    const float* x = (const float*)d_in[0];   // [4,4096,2048] f32
    const float* p = (const float*)d_in[1];   // [64,2048] f32
    float* out = (float*)d_out;

    const int ntok = in_sizes[0] / D;         // 16384
    const int write_idx = (out_size >= 4 * ntok) ? 1 : 0;
    float* out_i = out + 2 * ntok;

    cudaFuncSetAttribute(router_kernel, cudaFuncAttributeMaxDynamicSharedMemorySize, SMEM_TOTAL);

    proto_prep_kernel<<<NEXP, 256>>>(p);
    router_kernel<<<ntok / BM, NTHR, SMEM_TOTAL>>>(x, out, out_i, write_idx);
}